// round 7
// baseline (speedup 1.0000x reference)
#include <cuda_runtime.h>
#include <cuda_bf16.h>
#include <stdint.h>

#define THREADS 512
#define TM 128

// device scratch
__device__ __align__(16) __nv_bfloat16 g_Wt[256 * 512];   // [n][k] decoder weights, bf16
__device__ __align__(16) __nv_bfloat16 g_Wp2[256 * 256];  // [p*16+c][k] head weights, bf16
__device__ float g_sums[16];
__device__ float g_cnts[16];
__device__ int g_done;

// SMEM layout (bytes)
#define SM_A0 0
#define SM_A1 8192
#define SM_B0 16384
#define SM_B1 32768
#define SM_H 49152         // 8 blocks x [128 rows x 32 cols] bf16 = 64KB
#define SM_LG 114688       // 128*17 floats
#define SM_BIAS 123392
#define SM_BPRED 124416
#define SM_EM 125440
#define SM_SPAIR 126976
#define SM_SLABEL 127488
#define SM_PSUM 128000
#define SM_PCNT 128064
#define SMEM_TOTAL 128128

// 64B-row swizzle: 16B chunk c of row r stored at chunk position c ^ ((r>>1)&3)
#define SZB(r, c) ((((c) ^ (((r) >> 1) & 3)) << 4))

__global__ void prep_kernel(const float* __restrict__ W1, const float* __restrict__ W2,
                            const float* __restrict__ Wp) {
  int i = blockIdx.x * blockDim.x + threadIdx.x;
  if (i < 256 * 512) {
    int n = i >> 9, k = i & 511;
    float v = (k < 256) ? W1[k * 256 + n] : W2[(k - 256) * 256 + n];
    g_Wt[n * 512 + k] = __float2bfloat16(v);
  }
  if (i < 256 * 256) {
    int col = i >> 8, k = i & 255;
    int p = col >> 4, c = col & 15;
    g_Wp2[col * 256 + k] = __float2bfloat16(Wp[p * 4096 + k * 16 + c]);
  }
  if (i < 16) { g_sums[i] = 0.f; g_cnts[i] = 0.f; }
  if (i == 0) g_done = 0;
}

__device__ __forceinline__ void mma16816(float* c, uint32_t a0, uint32_t a1, uint32_t a2,
                                         uint32_t a3, uint32_t b0, uint32_t b1) {
  asm volatile(
      "mma.sync.aligned.m16n8k16.row.col.f32.bf16.bf16.f32 "
      "{%0,%1,%2,%3}, {%4,%5,%6,%7}, {%8,%9}, {%0,%1,%2,%3};\n"
      : "+f"(c[0]), "+f"(c[1]), "+f"(c[2]), "+f"(c[3])
      : "r"(a0), "r"(a1), "r"(a2), "r"(a3), "r"(b0), "r"(b1));
}

__device__ __forceinline__ void ldsm4(uint32_t& r0, uint32_t& r1, uint32_t& r2, uint32_t& r3,
                                      uint32_t a) {
  asm volatile("ldmatrix.sync.aligned.m8n8.x4.shared.b16 {%0,%1,%2,%3}, [%4];"
               : "=r"(r0), "=r"(r1), "=r"(r2), "=r"(r3)
               : "r"(a));
}

__device__ __forceinline__ uint32_t s2u(const void* p) {
  uint32_t a;
  asm("{ .reg .u64 t; cvta.to.shared.u64 t, %1; cvt.u32.u64 %0, t; }" : "=r"(a) : "l"(p));
  return a;
}

__device__ __forceinline__ uint4 pack8(float4 a, float4 b) {
  __nv_bfloat162 p0 = __floats2bfloat162_rn(a.x, a.y);
  __nv_bfloat162 p1 = __floats2bfloat162_rn(a.z, a.w);
  __nv_bfloat162 p2 = __floats2bfloat162_rn(b.x, b.y);
  __nv_bfloat162 p3 = __floats2bfloat162_rn(b.z, b.w);
  uint4 u;
  u.x = *(uint32_t*)&p0; u.y = *(uint32_t*)&p1;
  u.z = *(uint32_t*)&p2; u.w = *(uint32_t*)&p3;
  return u;
}

// A chunk [128 rows][32 k]: thread t -> row t>>2, chunk q=t&3 (8 k = 16B)
__device__ __forceinline__ uint4 loadA(const float* hs, const float* hd, long e0, int c, int t,
                                       int E) {
  int row = t >> 2, q = t & 3;
  long e = e0 + row; if (e >= E) e = E - 1;
  int kg = c * 32 + q * 8;
  const float* p = (kg < 256) ? hs + e * 256 + kg : hd + e * 256 + (kg - 256);
  float4 f0 = *(const float4*)(p);
  float4 f1 = *(const float4*)(p + 4);
  return pack8(f0, f1);
}
__device__ __forceinline__ void storeA(char* smem, uint32_t off, uint4 v, int t) {
  int row = t >> 2, q = t & 3;
  *(uint4*)(smem + off + row * 64 + SZB(row, q)) = v;
}
// B chunk [256 rows][32 k]: thread t -> row t>>1, half t&1 (2 chunks of 16B)
__device__ __forceinline__ void loadB(const __nv_bfloat16* src, int ldk, int koff, int t,
                                      uint4& v0, uint4& v1) {
  int row = t >> 1, h = t & 1;
  const uint4* s = (const uint4*)(src + row * ldk + koff + h * 16);
  v0 = s[0];
  v1 = s[1];
}
__device__ __forceinline__ void storeB(char* smem, uint32_t off, uint4 v0, uint4 v1, int t) {
  int row = t >> 1, h = t & 1;
  char* base = smem + off + row * 64;
  *(uint4*)(base + SZB(row, 2 * h)) = v0;
  *(uint4*)(base + SZB(row, 2 * h + 1)) = v1;
}

__global__ __launch_bounds__(THREADS, 1)
void main_kernel(const float* __restrict__ h_src, const float* __restrict__ h_dst,
                 const float* __restrict__ b_dec, const float* __restrict__ b_pred,
                 const int* __restrict__ st, const int* __restrict__ dt,
                 const int* __restrict__ etc, const int* __restrict__ emap,
                 float* __restrict__ out, int E) {
  extern __shared__ __align__(16) char smem[];
  const int tid = threadIdx.x;
  const int warp = tid >> 5, lane = tid & 31;
  const int wm = warp & 3, wn = warp >> 2;
  const long e0 = (long)blockIdx.x * TM;
  const uint32_t su = s2u(smem);

  float* bias = (float*)(smem + SM_BIAS);
  float* bpred = (float*)(smem + SM_BPRED);
  int* em = (int*)(smem + SM_EM);
  int* spair = (int*)(smem + SM_SPAIR);
  int* slabel = (int*)(smem + SM_SLABEL);
  float* psum = (float*)(smem + SM_PSUM);
  int* pcnt = (int*)(smem + SM_PCNT);
  float* Lg = (float*)(smem + SM_LG);

  for (int i = tid; i < 256; i += THREADS) { bias[i] = b_dec[i]; bpred[i] = b_pred[i]; }
  for (int i = tid; i < 384; i += THREADS) em[i] = emap[i];
  if (tid < 16) { psum[tid] = 0.f; pcnt[tid] = 0; }
  __syncthreads();
  if (tid < 128) {
    long e = e0 + tid; if (e >= E) e = E - 1;
    int p = st[e] * 4 + dt[e];
    spair[tid] = p;
    slabel[tid] = em[p * 24 + etc[e]];
  }

  // fragment LDSM lane addressing (constant per thread)
  const int a_rowrel = lane & 15;          // A: rows R0 + (lane&15)
  const int a_half = lane >> 4;            // A: k-half
  const int b_rowrel = ((lane & 16) >> 1) + (lane & 7);  // B: +8 if lane>=16
  const int b_half = (lane >> 3) & 1;      // B: k-half

  // ---- GEMM1: h = relu([h_src|h_dst] @ Wt^T + b), KC=32, 16 iters, double buffered ----
  float acc[2][8][4];
#pragma unroll
  for (int a = 0; a < 2; a++)
#pragma unroll
    for (int b = 0; b < 8; b++)
#pragma unroll
      for (int c = 0; c < 4; c++) acc[a][b][c] = 0.f;

  {
    uint4 av = loadA(h_src, h_dst, e0, 0, tid, E);
    uint4 bv0, bv1;
    loadB(g_Wt, 512, 0, tid, bv0, bv1);
    storeA(smem, SM_A0, av, tid);
    storeB(smem, SM_B0, bv0, bv1, tid);
  }
  __syncthreads();

  uint4 av, bv0, bv1;
  for (int it = 0; it < 16; ++it) {
    const int cur = it & 1;
    const bool more = (it + 1 < 16);
    if (more) {
      av = loadA(h_src, h_dst, e0, it + 1, tid, E);
      loadB(g_Wt, 512, (it + 1) * 32, tid, bv0, bv1);
    } else {
      // prefetch GEMM2 B chunk 0 instead
      loadB(g_Wp2, 256, 0, tid, bv0, bv1);
    }
    const uint32_t Ab = su + (cur ? SM_A1 : SM_A0);
    const uint32_t Bb = su + (cur ? SM_B1 : SM_B0);
#pragma unroll
    for (int ks = 0; ks < 2; ++ks) {
      uint32_t af[2][4];
#pragma unroll
      for (int mi = 0; mi < 2; ++mi) {
        int r = wm * 32 + mi * 16 + a_rowrel;
        ldsm4(af[mi][0], af[mi][1], af[mi][2], af[mi][3],
              Ab + r * 64 + SZB(r, 2 * ks + a_half));
      }
#pragma unroll
      for (int np = 0; np < 4; ++np) {
        int n = wn * 64 + np * 16 + b_rowrel;
        uint32_t b0, b1, b2, b3;
        ldsm4(b0, b1, b2, b3, Bb + n * 64 + SZB(n, 2 * ks + b_half));
        mma16816(acc[0][np * 2], af[0][0], af[0][1], af[0][2], af[0][3], b0, b1);
        mma16816(acc[1][np * 2], af[1][0], af[1][1], af[1][2], af[1][3], b0, b1);
        mma16816(acc[0][np * 2 + 1], af[0][0], af[0][1], af[0][2], af[0][3], b2, b3);
        mma16816(acc[1][np * 2 + 1], af[1][0], af[1][1], af[1][2], af[1][3], b2, b3);
      }
    }
    if (more) {
      storeA(smem, cur ? SM_A0 : SM_A1, av, tid);
      storeB(smem, cur ? SM_B0 : SM_B1, bv0, bv1, tid);
    }
    __syncthreads();
  }

  // stage GEMM2 B chunk 0 (prefetched above) into B0
  storeB(smem, SM_B0, bv0, bv1, tid);

  // epilogue: bias + relu -> h (swizzled 32-col blocks)
  {
    const int rb = lane >> 2;
#pragma unroll
    for (int mi = 0; mi < 2; ++mi) {
#pragma unroll
      for (int ni = 0; ni < 8; ++ni) {
        int n0 = wn * 64 + ni * 8 + (lane & 3) * 2;
        int kb = n0 >> 5, col = n0 & 31;
        int cch = col >> 3, coff = (col & 7) * 2;
        float bb0 = bias[n0], bb1 = bias[n0 + 1];
#pragma unroll
        for (int jp = 0; jp < 2; ++jp) {
          int r = wm * 32 + mi * 16 + rb + jp * 8;
          float v0 = fmaxf(acc[mi][ni][jp * 2] + bb0, 0.f);
          float v1 = fmaxf(acc[mi][ni][jp * 2 + 1] + bb1, 0.f);
          __nv_bfloat162 q = __floats2bfloat162_rn(v0, v1);
          *(uint32_t*)(smem + SM_H + kb * 8192 + r * 64 + SZB(r, cch) + coff) = *(uint32_t*)&q;
        }
      }
    }
  }
  __syncthreads();

  // ---- GEMM2: logits_all = h @ Wp2^T, KC=32, 8 iters ----
  float ac2[2][8][4];
#pragma unroll
  for (int a = 0; a < 2; a++)
#pragma unroll
    for (int b = 0; b < 8; b++)
#pragma unroll
      for (int c = 0; c < 4; c++) ac2[a][b][c] = 0.f;

  for (int it = 0; it < 8; ++it) {
    const int cur = it & 1;
    const bool more = (it + 1 < 8);
    if (more) loadB(g_Wp2, 256, (it + 1) * 32, tid, bv0, bv1);
    const uint32_t Ab = su + SM_H + it * 8192;
    const uint32_t Bb = su + (cur ? SM_B1 : SM_B0);
#pragma unroll
    for (int ks = 0; ks < 2; ++ks) {
      uint32_t af[2][4];
#pragma unroll
      for (int mi = 0; mi < 2; ++mi) {
        int r = wm * 32 + mi * 16 + a_rowrel;
        ldsm4(af[mi][0], af[mi][1], af[mi][2], af[mi][3],
              Ab + r * 64 + SZB(r, 2 * ks + a_half));
      }
#pragma unroll
      for (int np = 0; np < 4; ++np) {
        int n = wn * 64 + np * 16 + b_rowrel;
        uint32_t b0, b1, b2, b3;
        ldsm4(b0, b1, b2, b3, Bb + n * 64 + SZB(n, 2 * ks + b_half));
        mma16816(ac2[0][np * 2], af[0][0], af[0][1], af[0][2], af[0][3], b0, b1);
        mma16816(ac2[1][np * 2], af[1][0], af[1][1], af[1][2], af[1][3], b0, b1);
        mma16816(ac2[0][np * 2 + 1], af[0][0], af[0][1], af[0][2], af[0][3], b2, b3);
        mma16816(ac2[1][np * 2 + 1], af[1][0], af[1][1], af[1][2], af[1][3], b2, b3);
      }
    }
    if (more) storeB(smem, cur ? SM_B0 : SM_B1, bv0, bv1, tid);
    __syncthreads();
  }

  // select each edge's pair columns into Lg
  {
    const int rb = lane >> 2;
#pragma unroll
    for (int mi = 0; mi < 2; ++mi) {
      int r = wm * 32 + mi * 16 + rb;
      int plo = spair[r] * 16, phi = spair[r + 8] * 16;
#pragma unroll
      for (int ni = 0; ni < 8; ++ni) {
        int n0 = wn * 64 + ni * 8 + (lane & 3) * 2;
#pragma unroll
        for (int jj = 0; jj < 2; ++jj) {
          int c = n0 + jj;
          float bp = bpred[c];
          int cl = c - plo;
          if ((unsigned)cl < 16u) Lg[r * 17 + cl] = ac2[mi][ni][jj] + bp;
          int ch = c - phi;
          if ((unsigned)ch < 16u) Lg[(r + 8) * 17 + ch] = ac2[mi][ni][jj + 2] + bp;
        }
      }
    }
  }
  __syncthreads();

  // per-edge softmax NLL + per-pair partials
  if (tid < 128) {
    long e = e0 + tid;
    if (e < E) {
      const float* L = Lg + tid * 17;
      float mx = -1e30f;
#pragma unroll
      for (int c = 0; c < 16; ++c) mx = fmaxf(mx, L[c]);
      float s = 0.f;
#pragma unroll
      for (int c = 0; c < 16; ++c) s += __expf(L[c] - mx);
      float l = __logf(s) + mx - L[slabel[tid]];
      atomicAdd(&psum[spair[tid]], l);
      atomicAdd(&pcnt[spair[tid]], 1);
    }
  }
  __syncthreads();
  if (tid < 16 && pcnt[tid] > 0) {
    atomicAdd(&g_sums[tid], psum[tid]);
    atomicAdd(&g_cnts[tid], (float)pcnt[tid]);
  }
  __threadfence();
  __syncthreads();
  if (tid == 0) {
    int prev = atomicAdd(&g_done, 1);
    if (prev == (int)gridDim.x - 1) {
      __threadfence();
      float ls = 0.f, np = 0.f;
#pragma unroll
      for (int p = 0; p < 16; ++p) {
        float c = g_cnts[p];
        if (c > 0.f) { ls += g_sums[p] / c; np += 1.f; }
      }
      out[0] = ls / np;
    }
  }
}

extern "C" void kernel_launch(void* const* d_in, const int* in_sizes, int n_in,
                              void* d_out, int out_size) {
  const float* h_src = (const float*)d_in[0];
  const float* h_dst = (const float*)d_in[1];
  const float* W1 = (const float*)d_in[2];
  const float* W2 = (const float*)d_in[3];
  const float* b_dec = (const float*)d_in[4];
  const float* W_pred = (const float*)d_in[5];
  const float* b_pred = (const float*)d_in[6];
  const int* st = (const int*)d_in[7];
  const int* dt = (const int*)d_in[8];
  const int* etc = (const int*)d_in[9];
  const int* em = (const int*)d_in[10];
  int E = in_sizes[7];

  cudaFuncSetAttribute(main_kernel, cudaFuncAttributeMaxDynamicSharedMemorySize, SMEM_TOTAL);
  prep_kernel<<<512, 256>>>(W1, W2, W_pred);
  int grid = (E + TM - 1) / TM;
  main_kernel<<<grid, THREADS, SMEM_TOTAL>>>(h_src, h_dst, b_dec, b_pred, st, dt, etc, em,
                                             (float*)d_out, E);
}